// round 1
// baseline (speedup 1.0000x reference)
#include <cuda_runtime.h>

// AELoss: pred/target (64,4,256,256) fp32, match (64,128,2,2) int32.
// out[0] = 0.25 * sum_b pull_b, out[1] = 0.25 * sum_b push_b
//
// pull_b = sum_{n,c} (tl-br)^2 / 2 / N
// push_b = sum_{i!=j} relu(1 - |s_i - s_j|) / (N*(N-1)),  s_i = sum_c (tl+br)/2

#define B_IMGS 64
#define N_KP   128
#define C_CH   4
#define HW     65536   // 256*256
#define W_DIM  256

__device__ float g_scratch[2 * B_IMGS];  // [0..63]=pull, [64..127]=push

__global__ __launch_bounds__(N_KP, 1)
void ae_per_image_kernel(const float* __restrict__ pred,
                         const float* __restrict__ target,
                         const int*   __restrict__ match) {
    const int b = blockIdx.x;
    const int n = threadIdx.x;

    __shared__ float s_me[N_KP];
    __shared__ float s_red[8];  // 4 warps x 2 values

    // match[b, n, {tl,br}, {y,x}]
    const int4 m = __ldg(reinterpret_cast<const int4*>(match) + b * N_KP + n);
    const int tl_off = m.x * W_DIM + m.y;  // tl_y*W + tl_x
    const int br_off = m.z * W_DIM + m.w;  // br_y*W + br_x

    const float* __restrict__ p = pred   + (size_t)b * C_CH * HW;
    const float* __restrict__ t = target + (size_t)b * C_CH * HW;

    float pull = 0.0f;
    float s    = 0.0f;
    #pragma unroll
    for (int c = 0; c < C_CH; ++c) {
        const float tl = __ldg(p + c * HW + tl_off);
        const float br = __ldg(t + c * HW + br_off);
        const float d = tl - br;
        pull += 0.5f * d * d;
        s    += 0.5f * (tl + br);
    }
    s_me[n] = s;
    __syncthreads();

    // push: sum over all j (broadcast reads), subtract the j==n term (==1)
    float push = 0.0f;
    #pragma unroll 8
    for (int j = 0; j < N_KP; ++j) {
        push += fmaxf(0.0f, 1.0f - fabsf(s - s_me[j]));
    }
    push -= 1.0f;

    // block reduction of (pull, push): warp shuffles then cross-warp via smem
    #pragma unroll
    for (int off = 16; off > 0; off >>= 1) {
        pull += __shfl_down_sync(0xFFFFFFFFu, pull, off);
        push += __shfl_down_sync(0xFFFFFFFFu, push, off);
    }
    const int warp = n >> 5;
    const int lane = n & 31;
    if (lane == 0) {
        s_red[warp]     = pull;
        s_red[4 + warp] = push;
    }
    __syncthreads();
    if (n == 0) {
        float pu = s_red[0] + s_red[1] + s_red[2] + s_red[3];
        float ph = s_red[4] + s_red[5] + s_red[6] + s_red[7];
        g_scratch[b]          = pu / (float)N_KP;
        g_scratch[B_IMGS + b] = ph / (float)(N_KP * (N_KP - 1));
    }
}

__global__ void ae_reduce_kernel(float* __restrict__ out) {
    // one warp: lane i handles images {i, i+32}
    const int lane = threadIdx.x;
    float pu = g_scratch[lane] + g_scratch[lane + 32];
    float ph = g_scratch[B_IMGS + lane] + g_scratch[B_IMGS + lane + 32];
    #pragma unroll
    for (int off = 16; off > 0; off >>= 1) {
        pu += __shfl_down_sync(0xFFFFFFFFu, pu, off);
        ph += __shfl_down_sync(0xFFFFFFFFu, ph, off);
    }
    if (lane == 0) {
        out[0] = 0.25f * pu;
        out[1] = 0.25f * ph;
    }
}

extern "C" void kernel_launch(void* const* d_in, const int* in_sizes, int n_in,
                              void* d_out, int out_size) {
    const float* pred   = (const float*)d_in[0];
    const float* target = (const float*)d_in[1];
    const int*   match  = (const int*)d_in[2];
    float* out = (float*)d_out;

    ae_per_image_kernel<<<B_IMGS, N_KP>>>(pred, target, match);
    ae_reduce_kernel<<<1, 32>>>(out);
}

// round 2
// speedup vs baseline: 1.0037x; 1.0037x over previous
#include <cuda_runtime.h>

// AELoss fused single-launch version.
// pred/target (64,4,256,256) fp32, match (64,128,2,2) int32.
// out[0] = 0.25 * sum_b pull_b, out[1] = 0.25 * sum_b push_b
//
// pull_b = sum_{n,c} (tl-br)^2 / 2 / N        (since tl-me = (tl-br)/2)
// push_b = sum_{i!=j} relu(1 - |s_i - s_j|) / (N*(N-1)),  s_i = sum_c (tl+br)/2

#define B_IMGS 64
#define N_KP   128
#define C_CH   4
#define HW     65536   // 256*256
#define W_DIM  256

__device__ float g_scratch[2 * B_IMGS];   // [0..63]=pull_b, [64..127]=push_b
__device__ unsigned int g_count;          // zero-init at load; reset in-kernel

__global__ __launch_bounds__(N_KP, 1)
void ae_fused_kernel(const float* __restrict__ pred,
                     const float* __restrict__ target,
                     const int*   __restrict__ match,
                     float*       __restrict__ out) {
    const int b = blockIdx.x;
    const int n = threadIdx.x;

    __shared__ float s_me[N_KP];
    __shared__ float s_red[8];    // 4 warps x 2 values
    __shared__ int   s_last;

    // match[b, n, {tl,br}, {y,x}] -- one int4 per (b,n)
    const int4 m = __ldg(reinterpret_cast<const int4*>(match) + b * N_KP + n);
    const int tl_off = m.x * W_DIM + m.y;
    const int br_off = m.z * W_DIM + m.w;

    const float* __restrict__ p = pred   + (size_t)b * C_CH * HW;
    const float* __restrict__ t = target + (size_t)b * C_CH * HW;

    float pull = 0.0f;
    float s    = 0.0f;
    #pragma unroll
    for (int c = 0; c < C_CH; ++c) {
        const float tl = __ldg(p + c * HW + tl_off);
        const float br = __ldg(t + c * HW + br_off);
        const float d = tl - br;
        pull += 0.5f * d * d;
        s    += 0.5f * (tl + br);
    }
    s_me[n] = s;
    __syncthreads();

    // push: full sum over j (vectorized smem broadcast), minus the j==n term (==1)
    float push = -1.0f;
    const float4* __restrict__ s4 = reinterpret_cast<const float4*>(s_me);
    #pragma unroll
    for (int j = 0; j < N_KP / 4; ++j) {
        const float4 v = s4[j];
        push += fmaxf(0.0f, 1.0f - fabsf(s - v.x));
        push += fmaxf(0.0f, 1.0f - fabsf(s - v.y));
        push += fmaxf(0.0f, 1.0f - fabsf(s - v.z));
        push += fmaxf(0.0f, 1.0f - fabsf(s - v.w));
    }

    // block reduction of (pull, push)
    #pragma unroll
    for (int off = 16; off > 0; off >>= 1) {
        pull += __shfl_down_sync(0xFFFFFFFFu, pull, off);
        push += __shfl_down_sync(0xFFFFFFFFu, push, off);
    }
    const int warp = n >> 5;
    const int lane = n & 31;
    if (lane == 0) {
        s_red[warp]     = pull;
        s_red[4 + warp] = push;
    }
    __syncthreads();

    if (n == 0) {
        const float pu = s_red[0] + s_red[1] + s_red[2] + s_red[3];
        const float ph = s_red[4] + s_red[5] + s_red[6] + s_red[7];
        // L1-bypassing stores so the last block reads fresh values from L2
        __stcg(&g_scratch[b],          pu * (1.0f / (float)N_KP));
        __stcg(&g_scratch[B_IMGS + b], ph * (1.0f / (float)(N_KP * (N_KP - 1))));
        __threadfence();
        const unsigned int old = atomicAdd(&g_count, 1u);
        s_last = (old == (unsigned)(B_IMGS - 1)) ? 1 : 0;
    }
    __syncthreads();

    // Last block to finish performs the final deterministic reduction.
    if (s_last && warp == 0) {
        __threadfence();  // acquire side: order g_scratch reads after the atomic
        float pu = __ldcg(&g_scratch[lane]) + __ldcg(&g_scratch[lane + 32]);
        float ph = __ldcg(&g_scratch[B_IMGS + lane]) + __ldcg(&g_scratch[B_IMGS + lane + 32]);
        #pragma unroll
        for (int off = 16; off > 0; off >>= 1) {
            pu += __shfl_down_sync(0xFFFFFFFFu, pu, off);
            ph += __shfl_down_sync(0xFFFFFFFFu, ph, off);
        }
        if (lane == 0) {
            out[0] = 0.25f * pu;
            out[1] = 0.25f * ph;
            g_count = 0;   // reset for next graph replay
        }
    }
}

extern "C" void kernel_launch(void* const* d_in, const int* in_sizes, int n_in,
                              void* d_out, int out_size) {
    const float* pred   = (const float*)d_in[0];
    const float* target = (const float*)d_in[1];
    const int*   match  = (const int*)d_in[2];
    float* out = (float*)d_out;

    ae_fused_kernel<<<B_IMGS, N_KP>>>(pred, target, match, out);
}